// round 15
// baseline (speedup 1.0000x reference)
#include <cuda_runtime.h>
#include <cuda_fp16.h>
#include <cstdint>

#define KV_OFF   (64*8192*64)
#define KV_SIZE  (64*64*64)
#define NORM_OFF (KV_OFF + KV_SIZE)
#define EPSV 1e-10f
#define SH 72                     // halves per fp16 tile row (144B)
#define SF 68                     // floats per fp32 staging row

// half-index offsets for fp16 tiles
#define H_KV 0                    // 64 x SH shared past_kv
#define H_K  4608
#define H_V  9216
#define H_Q  13824
// byte offsets for fp32 staging buffers (each 64*SF*4 = 17408B)
#define STGK_B 36864
#define STGV_B 54272
#define STGQ_B 71680
#define STGO_B 89088
#define F_BASE_BYTES 106496       // sN[64], sIu[64], sIr[64], sNrm[64]
#define SMEM_BYTES (F_BASE_BYTES + 1024)

__device__ __forceinline__ float elu1(float x){ return x > 0.f ? x + 1.f : __expf(x); }
__device__ __forceinline__ uint32_t s2u(const void* p){ return (uint32_t)__cvta_generic_to_shared(p); }
__device__ __forceinline__ void bar256(){ asm volatile("bar.sync 1, 256;" ::: "memory"); }
__device__ __forceinline__ void bar128(){ asm volatile("bar.sync 2, 128;" ::: "memory"); }
__device__ __forceinline__ uint32_t h2u(__half2 h){ return *reinterpret_cast<uint32_t*>(&h); }
__device__ __forceinline__ void cpa16(uint32_t s, const void* g){
    asm volatile("cp.async.cg.shared.global [%0], [%1], 16;" :: "r"(s), "l"(g));
}
#define CP_COMMIT() asm volatile("cp.async.commit_group;")
#define CP_WAIT(n)  asm volatile("cp.async.wait_group %0;" :: "n"(n))

__device__ __forceinline__ void ldsm4(uint32_t& r0,uint32_t& r1,uint32_t& r2,uint32_t& r3,uint32_t a){
    asm volatile("ldmatrix.sync.aligned.m8n8.x4.shared.b16 {%0,%1,%2,%3},[%4];"
                 : "=r"(r0),"=r"(r1),"=r"(r2),"=r"(r3) : "r"(a));
}
__device__ __forceinline__ void ldsm4t(uint32_t& r0,uint32_t& r1,uint32_t& r2,uint32_t& r3,uint32_t a){
    asm volatile("ldmatrix.sync.aligned.m8n8.x4.trans.shared.b16 {%0,%1,%2,%3},[%4];"
                 : "=r"(r0),"=r"(r1),"=r"(r2),"=r"(r3) : "r"(a));
}
__device__ __forceinline__ void mma16(float& c0,float& c1,float& c2,float& c3,
                                      uint32_t a0,uint32_t a1,uint32_t a2,uint32_t a3,
                                      uint32_t b0,uint32_t b1){
    asm("mma.sync.aligned.m16n8k16.row.col.f32.f16.f16.f32 "
        "{%0,%1,%2,%3},{%4,%5,%6,%7},{%8,%9},{%0,%1,%2,%3};"
        : "+f"(c0),"+f"(c1),"+f"(c2),"+f"(c3)
        : "r"(a0),"r"(a1),"r"(a2),"r"(a3),"r"(b0),"r"(b1));
}

// ---- 128-thread staging: 8 x 16B per thread ----
__device__ __forceinline__ void cp_fill128(const float* __restrict__ g,
                                           float* __restrict__ stg, int tg){
#pragma unroll
    for (int i = 0; i < 8; i++){
        int f = tg + (i << 7);
        int n = f >> 4, c4 = (f & 15) << 2;
        cpa16(s2u(&stg[n*SF + c4]), &g[(n << 6) + c4]);
    }
    CP_COMMIT();
}
// ---- 256-thread staging: 4 x 16B per thread ----
__device__ __forceinline__ void cp_fill256(const float* __restrict__ g,
                                           float* __restrict__ stg, int tg2){
#pragma unroll
    for (int i = 0; i < 4; i++){
        int f = tg2 + (i << 8);
        int n = f >> 4, c4 = (f & 15) << 2;
        cpa16(s2u(&stg[n*SF + c4]), &g[(n << 6) + c4]);
    }
    CP_COMMIT();
}

// fp32 staging -> elu+1 -> fp16, fused butterfly denominators.
// 128-thread version: 8 rows/thread (rows nb+8i, matching cp_fill128).
__device__ __forceinline__ void cvt_denom128(const float* __restrict__ stg,
                                             __half* __restrict__ dst, int tg, int lane,
                                             float n0f, float n1f, float n2f, float n3f,
                                             float* __restrict__ sI){
    const int nb = tg >> 4, c4 = (tg & 15) << 2;
    float rp[8];
#pragma unroll
    for (int i = 0; i < 8; i++){
        const int n = nb + (i << 3);
        float4 v = *(const float4*)&stg[n*SF + c4];
        v.x = elu1(v.x); v.y = elu1(v.y); v.z = elu1(v.z); v.w = elu1(v.w);
        float t = v.x * n0f;
        t = fmaf(v.y, n1f, t); t = fmaf(v.z, n2f, t); t = fmaf(v.w, n3f, t);
        rp[i] = t;
        uint2 u;
        u.x = h2u(__floats2half2_rn(v.x, v.y));
        u.y = h2u(__floats2half2_rn(v.z, v.w));
        *(uint2*)&dst[n*SH + c4] = u;
    }
#pragma unroll
    for (int m = 1; m < 16; m <<= 1)
#pragma unroll
        for (int i = 0; i < 8; i++)
            rp[i] += __shfl_xor_sync(0xffffffffu, rp[i], m);
    if ((lane & 15) == 0)
#pragma unroll
        for (int i = 0; i < 8; i++)
            sI[nb + (i << 3)] = 1.f / fmaxf(rp[i], EPSV);
}
// 256-thread version: 4 rows/thread (rows (t>>4)+16i); accumulates new_norm.
__device__ __forceinline__ void cvt_denom256(const float* __restrict__ stg,
                                             __half* __restrict__ dst, int tg2, int lane,
                                             float n0f, float n1f, float n2f, float n3f,
                                             float* __restrict__ sI, float (&nrm)[4]){
    const int nb = tg2 >> 4, c4 = (tg2 & 15) << 2;
    float rp[4];
#pragma unroll
    for (int i = 0; i < 4; i++){
        const int n = nb + (i << 4);
        float4 v = *(const float4*)&stg[n*SF + c4];
        v.x = elu1(v.x); v.y = elu1(v.y); v.z = elu1(v.z); v.w = elu1(v.w);
        nrm[0] += v.x; nrm[1] += v.y; nrm[2] += v.z; nrm[3] += v.w;
        float t = v.x * n0f;
        t = fmaf(v.y, n1f, t); t = fmaf(v.z, n2f, t); t = fmaf(v.w, n3f, t);
        rp[i] = t;
        uint2 u;
        u.x = h2u(__floats2half2_rn(v.x, v.y));
        u.y = h2u(__floats2half2_rn(v.z, v.w));
        *(uint2*)&dst[n*SH + c4] = u;
    }
#pragma unroll
    for (int m = 1; m < 16; m <<= 1)
#pragma unroll
        for (int i = 0; i < 4; i++)
            rp[i] += __shfl_xor_sync(0xffffffffu, rp[i], m);
    if ((lane & 15) == 0)
#pragma unroll
        for (int i = 0; i < 4; i++)
            sI[nb + (i << 4)] = 1.f / fmaxf(rp[i], EPSV);
}

__global__ void init_tail(const float* __restrict__ pkv,
                          const float* __restrict__ pnorm,
                          float* __restrict__ dout){
    int i = blockIdx.x * 256 + threadIdx.x;
    if (i < KV_SIZE) dout[KV_OFF + i]   = pkv[i];
    if (i < 64*64)   dout[NORM_OFF + i] = pnorm[i];
}

__global__ void __launch_bounds__(384, 2) fw_kernel(
    const float* __restrict__ keys, const float* __restrict__ values,
    const float* __restrict__ queries, const float* __restrict__ outin,
    const float* __restrict__ pkv, const float* __restrict__ pnorm,
    const float* __restrict__ gates, float* __restrict__ dout)
{
    extern __shared__ __align__(16) char smraw[];
    __half* smh = (__half*)smraw;
    float*  smf = (float*)(smraw + F_BASE_BYTES);
    float* sN   = smf;
    float* sNrm = smf + 192;

    const int tid = threadIdx.x;
    const int lane = tid & 31;
    const int gid = lane >> 2, tig = lane & 3;
    const int bh  = blockIdx.y;
    const size_t gOff = (size_t)bh * (8192*64);
    const int rowBase = blockIdx.x * 256;

    __half* sKV = smh + H_KV;

    // ldmatrix lane geometry
    const int ar  = (((lane>>3)&1) << 3) + (lane & 7);
    const int ac  = (lane >> 4) << 3;
    const int ar2 = ((lane >> 4) << 3) + (lane & 7);
    const int ac2 = ((lane >> 3) & 1) << 3;
    const uint32_t bKV = s2u(&sKV[ar*SH + ac]);

    // ---- shared prologue: past_kv -> fp16, norm, zero sNrm ----
#pragma unroll
    for (int i = 0; i < 3; i++){
        int f = tid + i * 384;
        if (f < 1024){
            int n = f >> 4, c4 = (f & 15) << 2;
            float4 v = *(const float4*)&pkv[(size_t)bh*4096 + (n << 6) + c4];
            uint2 u;
            u.x = h2u(__floats2half2_rn(v.x, v.y));
            u.y = h2u(__floats2half2_rn(v.z, v.w));
            *(uint2*)&sKV[n*SH + c4] = u;
        }
    }
    if (tid < 64){ sN[tid] = pnorm[bh*64 + tid]; sNrm[tid] = 0.f; }

    const float et  = __expf(-gates[bh & 15]);
    const float gte = 1.f/(1.f+et), omg = et/(1.f+et);

    if (tid < 256){
        // ========== UPDATE GROUP (8 warps): k,v -> new_kv,new_norm ==========
        const int tg2 = tid;
        const int w   = tid >> 5;
        const int m0  = (w & 3) << 4;
        const int coh = (w >> 2) << 5;
        __half* sK = smh + H_K;
        __half* sV = smh + H_V;
        float* stgK = (float*)(smraw + STGK_B);
        float* stgV = (float*)(smraw + STGV_B);
        float* sI  = smf + 64;
        const uint32_t aK  = s2u(&sK[(m0 + ar)*SH + ac]);
        const uint32_t aK2 = s2u(&sK[ar2*SH + m0 + ac2]);
        const uint32_t bV  = s2u(&sV[ar*SH + coh + ac]);
        const uint32_t bKVu = s2u(&sKV[ar*SH + coh + ac]);

        cp_fill256(keys   + gOff + (size_t)rowBase*64, stgK, tg2);
        cp_fill256(values + gOff + (size_t)rowBase*64, stgV, tg2);
        __syncthreads();
        const int c4t = (tg2 & 15) << 2;
        const float n0f = sN[c4t], n1f = sN[c4t+1], n2f = sN[c4t+2], n3f = sN[c4t+3];

        float acc[4][4];
#pragma unroll
        for (int a = 0; a < 4; a++){ acc[a][0]=0.f; acc[a][1]=0.f; acc[a][2]=0.f; acc[a][3]=0.f; }
        float nrm[4] = {0.f, 0.f, 0.f, 0.f};

        for (int ch = 0; ch < 4; ++ch){
            const int row0 = rowBase + (ch << 6);

            // A: k(ch) ready; cvt+denom; prefetch k(ch+1); drain v(ch); barrier
            CP_WAIT(1);
            cvt_denom256(stgK, sK, tg2, lane, n0f, n1f, n2f, n3f, sI, nrm);
            if (ch < 3){
                cp_fill256(keys + gOff + (size_t)(row0+64)*64, stgK, tg2);
                CP_WAIT(1);
            } else {
                CP_WAIT(0);
            }
            bar256();

            // B: GEMM1 quadrant (16 rows x 32 cols) + fused v-update
            {
                const float i1 = sI[m0+gid], i2 = sI[m0+gid+8];
                float c[4][4];
#pragma unroll
                for (int nt = 0; nt < 4; nt++){ c[nt][0]=0.f; c[nt][1]=0.f; c[nt][2]=0.f; c[nt][3]=0.f; }
#pragma unroll
                for (int ks = 0; ks < 4; ks++){
                    const int k0 = ks << 4;
                    uint32_t a0,a1,a2,a3;
                    ldsm4(a0,a1,a2,a3, aK + (k0 << 1));
#pragma unroll
                    for (int ntp = 0; ntp < 2; ntp++){
                        uint32_t b0,b1,b2,b3;
                        ldsm4t(b0,b1,b2,b3, bKVu + ((k0*SH + (ntp<<4)) << 1));
                        mma16(c[2*ntp][0],c[2*ntp][1],c[2*ntp][2],c[2*ntp][3],
                              a0,a1,a2,a3, b0,b1);
                        mma16(c[2*ntp+1][0],c[2*ntp+1][1],c[2*ntp+1][2],c[2*ntp+1][3],
                              a0,a1,a2,a3, b2,b3);
                    }
                }
#pragma unroll
                for (int nt = 0; nt < 4; nt++){
                    const int cc = coh + (nt<<3) + (tig<<1);
                    const float2 v1 = *(const float2*)&stgV[(m0+gid)*SF + cc];
                    const float2 v2 = *(const float2*)&stgV[(m0+gid+8)*SF + cc];
                    __half2 h1 = __floats2half2_rn(v1.x - c[nt][0]*i1,
                                                   v1.y - c[nt][1]*i1);
                    __half2 h2 = __floats2half2_rn(v2.x - c[nt][2]*i2,
                                                   v2.y - c[nt][3]*i2);
                    *(uint32_t*)&sV[(m0+gid)*SH + cc]   = h2u(h1);
                    *(uint32_t*)&sV[(m0+gid+8)*SH + cc] = h2u(h2);
                }
            }
            bar256();
            if (ch < 3)
                cp_fill256(values + gOff + (size_t)(row0+64)*64, stgV, tg2);

            // C: GEMM2 quadrant acc += k^T v (16 d x 32 e)
#pragma unroll
            for (int ks = 0; ks < 4; ks++){
                const int k0 = ks << 4;
                uint32_t a0,a1,a2,a3;
                ldsm4t(a0,a1,a2,a3, aK2 + ((k0*SH) << 1));
#pragma unroll
                for (int ntp = 0; ntp < 2; ntp++){
                    uint32_t b0,b1,b2,b3;
                    ldsm4t(b0,b1,b2,b3, bV + ((k0*SH + (ntp<<4)) << 1));
                    mma16(acc[2*ntp][0],acc[2*ntp][1],acc[2*ntp][2],acc[2*ntp][3],
                          a0,a1,a2,a3, b0,b1);
                    mma16(acc[2*ntp+1][0],acc[2*ntp+1][1],acc[2*ntp+1][2],acc[2*ntp+1][3],
                          a0,a1,a2,a3, b2,b3);
                }
            }
            bar256();
        }

        // ---- flush new_kv / new_norm ----
#pragma unroll
        for (int j = 0; j < 4; j++) atomicAdd(&sNrm[c4t + j], nrm[j]);
        float* kvout = dout + KV_OFF + bh * 4096;
#pragma unroll
        for (int j = 0; j < 4; j++){
            const int cc = coh + (j<<3) + (tig<<1);
            float* r1 = &kvout[(m0+gid)*64 + cc];
            float* r2 = &kvout[(m0+gid+8)*64 + cc];
            atomicAdd(r1,   acc[j][0]); atomicAdd(r1+1, acc[j][1]);
            atomicAdd(r2,   acc[j][2]); atomicAdd(r2+1, acc[j][3]);
        }
        bar256();
        if (tg2 < 64) atomicAdd(&dout[NORM_OFF + bh*64 + tg2], sNrm[tg2]);
    } else {
        // ========== RETRIEVE GROUP (4 warps): q -> gated out ==========
        const int tg = tid & 127;
        const int n0 = ((tid >> 5) - 8) << 4;
        __half* sQ = smh + H_Q;
        float* stgQ = (float*)(smraw + STGQ_B);
        float* stgO = (float*)(smraw + STGO_B);
        float* sI  = smf + 128;
        const uint32_t aQ = s2u(&sQ[(n0 + ar)*SH + ac]);

        cp_fill128(queries + gOff + (size_t)rowBase*64, stgQ, tg);
        cp_fill128(outin   + gOff + (size_t)rowBase*64, stgO, tg);
        __syncthreads();
        const int c4t = (tg & 15) << 2;
        const float n0f = sN[c4t], n1f = sN[c4t+1], n2f = sN[c4t+2], n3f = sN[c4t+3];

        for (int ch = 0; ch < 4; ++ch){
            const int row0 = rowBase + (ch << 6);

            // A: q(ch) ready (o(ch) may still fly); cvt+denom; prefetch q(ch+1)
            CP_WAIT(1);
            cvt_denom128(stgQ, sQ, tg, lane, n0f, n1f, n2f, n3f, sI);
            if (ch < 3)
                cp_fill128(queries + gOff + (size_t)(row0+64)*64, stgQ, tg);
            bar128();                 // publish sQ/sI; o(ch) drained later

            // B: GEMM3 (two 32-col passes) + gated epilogue from staged out.
            // o(ch) drain is deferred to after pass-0's MMA chain so its DRAM
            // latency is covered by tensor work instead of stalling phase A.
            const float s1 = sI[n0+gid]*omg, s2 = sI[n0+gid+8]*omg;
            const size_t r1 = gOff + (size_t)(row0+n0+gid)*64;
            const size_t r2 = r1 + 512;
#pragma unroll
            for (int pass = 0; pass < 2; pass++){
                float c[4][4];
#pragma unroll
                for (int nt = 0; nt < 4; nt++){ c[nt][0]=0.f; c[nt][1]=0.f; c[nt][2]=0.f; c[nt][3]=0.f; }
#pragma unroll
                for (int ks = 0; ks < 4; ks++){
                    const int k0 = ks << 4;
                    uint32_t a0,a1,a2,a3;
                    ldsm4(a0,a1,a2,a3, aQ + (k0 << 1));
#pragma unroll
                    for (int ntp = 0; ntp < 2; ntp++){
                        uint32_t b0,b1,b2,b3;
                        ldsm4t(b0,b1,b2,b3, bKV + ((k0*SH + (pass<<5) + (ntp<<4)) << 1));
                        mma16(c[2*ntp][0],c[2*ntp][1],c[2*ntp][2],c[2*ntp][3],
                              a0,a1,a2,a3, b0,b1);
                        mma16(c[2*ntp+1][0],c[2*ntp+1][1],c[2*ntp+1][2],c[2*ntp+1][3],
                              a0,a1,a2,a3, b2,b3);
                    }
                }
                if (pass == 0){
                    // late drain of o(ch): queue is [o(ch)] or [o(ch), q(ch+1)]
                    if (ch < 3){ CP_WAIT(1); } else { CP_WAIT(0); }
                    bar128();          // publish stgO to all retrieve threads
                }
#pragma unroll
                for (int nt = 0; nt < 4; nt++){
                    const int cc = (pass<<5) + (nt<<3) + (tig<<1);
                    float2 o1 = *(const float2*)&stgO[(n0+gid)*SF + cc];
                    float2 o2 = *(const float2*)&stgO[(n0+gid+8)*SF + cc];
                    o1.x = o1.x*gte + c[nt][0]*s1; o1.y = o1.y*gte + c[nt][1]*s1;
                    o2.x = o2.x*gte + c[nt][2]*s2; o2.y = o2.y*gte + c[nt][3]*s2;
                    *(float2*)&dout[r1 + cc] = o1;
                    *(float2*)&dout[r2 + cc] = o2;
                }
            }
            bar128();
            if (ch < 3)
                cp_fill128(outin + gOff + (size_t)(row0+64)*64, stgO, tg);
        }
    }
}

extern "C" void kernel_launch(void* const* d_in, const int* in_sizes, int n_in,
                              void* d_out, int out_size)
{
    const float* keys    = (const float*)d_in[0];
    const float* values  = (const float*)d_in[1];
    const float* queries = (const float*)d_in[2];
    const float* outin   = (const float*)d_in[3];
    const float* pkv     = (const float*)d_in[4];
    const float* pnorm   = (const float*)d_in[5];
    const float* gates   = (const float*)d_in[6];
    float* dout = (float*)d_out;

    cudaFuncSetAttribute(fw_kernel, cudaFuncAttributeMaxDynamicSharedMemorySize, SMEM_BYTES);

    init_tail<<<1024, 256>>>(pkv, pnorm, dout);
    fw_kernel<<<dim3(32, 64), 384, SMEM_BYTES>>>(keys, values, queries, outin,
                                                 pkv, pnorm, gates, dout);
}

// round 16
// speedup vs baseline: 1.0330x; 1.0330x over previous
#include <cuda_runtime.h>
#include <cuda_fp16.h>
#include <cstdint>

#define KV_OFF   (64*8192*64)
#define KV_SIZE  (64*64*64)
#define NORM_OFF (KV_OFF + KV_SIZE)
#define EPSV 1e-10f
#define SH 72                     // halves per fp16 tile row (144B)
#define SF 68                     // floats per fp32 staging row

// half-index offsets for fp16 tiles
#define H_KV 0                    // 64 x SH shared past_kv
#define H_K  4608
#define H_V  9216
#define H_Q  13824
// byte offsets for fp32 staging buffers (each 64*SF*4 = 17408B)
#define STGK_B 36864
#define STGV_B 54272
#define STGQ_B 71680
#define STGO_B 89088
#define F_BASE_BYTES 106496       // sN[64], sIu[64], sIr[64], sNrm[64]
#define SMEM_BYTES (F_BASE_BYTES + 1024)

__device__ __forceinline__ float elu1(float x){ return x > 0.f ? x + 1.f : __expf(x); }
__device__ __forceinline__ uint32_t s2u(const void* p){ return (uint32_t)__cvta_generic_to_shared(p); }
__device__ __forceinline__ void bar256(){ asm volatile("bar.sync 1, 256;" ::: "memory"); }
__device__ __forceinline__ void bar128(){ asm volatile("bar.sync 2, 128;" ::: "memory"); }
__device__ __forceinline__ uint32_t h2u(__half2 h){ return *reinterpret_cast<uint32_t*>(&h); }
// cp.async with 256B L2 prefetch hint: input streams are perfectly sequential,
// each warp covers 2KB contiguous, so prefetched sectors are always consumed.
__device__ __forceinline__ void cpa16(uint32_t s, const void* g){
    asm volatile("cp.async.cg.shared.global.L2::256B [%0], [%1], 16;" :: "r"(s), "l"(g));
}
#define CP_COMMIT() asm volatile("cp.async.commit_group;")
#define CP_WAIT(n)  asm volatile("cp.async.wait_group %0;" :: "n"(n))

__device__ __forceinline__ void ldsm4(uint32_t& r0,uint32_t& r1,uint32_t& r2,uint32_t& r3,uint32_t a){
    asm volatile("ldmatrix.sync.aligned.m8n8.x4.shared.b16 {%0,%1,%2,%3},[%4];"
                 : "=r"(r0),"=r"(r1),"=r"(r2),"=r"(r3) : "r"(a));
}
__device__ __forceinline__ void ldsm4t(uint32_t& r0,uint32_t& r1,uint32_t& r2,uint32_t& r3,uint32_t a){
    asm volatile("ldmatrix.sync.aligned.m8n8.x4.trans.shared.b16 {%0,%1,%2,%3},[%4];"
                 : "=r"(r0),"=r"(r1),"=r"(r2),"=r"(r3) : "r"(a));
}
__device__ __forceinline__ void mma16(float& c0,float& c1,float& c2,float& c3,
                                      uint32_t a0,uint32_t a1,uint32_t a2,uint32_t a3,
                                      uint32_t b0,uint32_t b1){
    asm("mma.sync.aligned.m16n8k16.row.col.f32.f16.f16.f32 "
        "{%0,%1,%2,%3},{%4,%5,%6,%7},{%8,%9},{%0,%1,%2,%3};"
        : "+f"(c0),"+f"(c1),"+f"(c2),"+f"(c3)
        : "r"(a0),"r"(a1),"r"(a2),"r"(a3),"r"(b0),"r"(b1));
}

// ---- 128-thread staging: 8 x 16B per thread ----
__device__ __forceinline__ void cp_fill128(const float* __restrict__ g,
                                           float* __restrict__ stg, int tg){
#pragma unroll
    for (int i = 0; i < 8; i++){
        int f = tg + (i << 7);
        int n = f >> 4, c4 = (f & 15) << 2;
        cpa16(s2u(&stg[n*SF + c4]), &g[(n << 6) + c4]);
    }
    CP_COMMIT();
}
// ---- 256-thread staging: 4 x 16B per thread ----
__device__ __forceinline__ void cp_fill256(const float* __restrict__ g,
                                           float* __restrict__ stg, int tg2){
#pragma unroll
    for (int i = 0; i < 4; i++){
        int f = tg2 + (i << 8);
        int n = f >> 4, c4 = (f & 15) << 2;
        cpa16(s2u(&stg[n*SF + c4]), &g[(n << 6) + c4]);
    }
    CP_COMMIT();
}

// fp32 staging -> elu+1 -> fp16, fused butterfly denominators.
// 128-thread version: 8 rows/thread (rows nb+8i, matching cp_fill128).
__device__ __forceinline__ void cvt_denom128(const float* __restrict__ stg,
                                             __half* __restrict__ dst, int tg, int lane,
                                             float n0f, float n1f, float n2f, float n3f,
                                             float* __restrict__ sI){
    const int nb = tg >> 4, c4 = (tg & 15) << 2;
    float rp[8];
#pragma unroll
    for (int i = 0; i < 8; i++){
        const int n = nb + (i << 3);
        float4 v = *(const float4*)&stg[n*SF + c4];
        v.x = elu1(v.x); v.y = elu1(v.y); v.z = elu1(v.z); v.w = elu1(v.w);
        float t = v.x * n0f;
        t = fmaf(v.y, n1f, t); t = fmaf(v.z, n2f, t); t = fmaf(v.w, n3f, t);
        rp[i] = t;
        uint2 u;
        u.x = h2u(__floats2half2_rn(v.x, v.y));
        u.y = h2u(__floats2half2_rn(v.z, v.w));
        *(uint2*)&dst[n*SH + c4] = u;
    }
#pragma unroll
    for (int m = 1; m < 16; m <<= 1)
#pragma unroll
        for (int i = 0; i < 8; i++)
            rp[i] += __shfl_xor_sync(0xffffffffu, rp[i], m);
    if ((lane & 15) == 0)
#pragma unroll
        for (int i = 0; i < 8; i++)
            sI[nb + (i << 3)] = 1.f / fmaxf(rp[i], EPSV);
}
// 256-thread version: 4 rows/thread (rows (t>>4)+16i); accumulates new_norm.
__device__ __forceinline__ void cvt_denom256(const float* __restrict__ stg,
                                             __half* __restrict__ dst, int tg2, int lane,
                                             float n0f, float n1f, float n2f, float n3f,
                                             float* __restrict__ sI, float (&nrm)[4]){
    const int nb = tg2 >> 4, c4 = (tg2 & 15) << 2;
    float rp[4];
#pragma unroll
    for (int i = 0; i < 4; i++){
        const int n = nb + (i << 4);
        float4 v = *(const float4*)&stg[n*SF + c4];
        v.x = elu1(v.x); v.y = elu1(v.y); v.z = elu1(v.z); v.w = elu1(v.w);
        nrm[0] += v.x; nrm[1] += v.y; nrm[2] += v.z; nrm[3] += v.w;
        float t = v.x * n0f;
        t = fmaf(v.y, n1f, t); t = fmaf(v.z, n2f, t); t = fmaf(v.w, n3f, t);
        rp[i] = t;
        uint2 u;
        u.x = h2u(__floats2half2_rn(v.x, v.y));
        u.y = h2u(__floats2half2_rn(v.z, v.w));
        *(uint2*)&dst[n*SH + c4] = u;
    }
#pragma unroll
    for (int m = 1; m < 16; m <<= 1)
#pragma unroll
        for (int i = 0; i < 4; i++)
            rp[i] += __shfl_xor_sync(0xffffffffu, rp[i], m);
    if ((lane & 15) == 0)
#pragma unroll
        for (int i = 0; i < 4; i++)
            sI[nb + (i << 4)] = 1.f / fmaxf(rp[i], EPSV);
}

__global__ void init_tail(const float* __restrict__ pkv,
                          const float* __restrict__ pnorm,
                          float* __restrict__ dout){
    int i = blockIdx.x * 256 + threadIdx.x;
    if (i < KV_SIZE) dout[KV_OFF + i]   = pkv[i];
    if (i < 64*64)   dout[NORM_OFF + i] = pnorm[i];
}

__global__ void __launch_bounds__(384, 2) fw_kernel(
    const float* __restrict__ keys, const float* __restrict__ values,
    const float* __restrict__ queries, const float* __restrict__ outin,
    const float* __restrict__ pkv, const float* __restrict__ pnorm,
    const float* __restrict__ gates, float* __restrict__ dout)
{
    extern __shared__ __align__(16) char smraw[];
    __half* smh = (__half*)smraw;
    float*  smf = (float*)(smraw + F_BASE_BYTES);
    float* sN   = smf;
    float* sNrm = smf + 192;

    const int tid = threadIdx.x;
    const int lane = tid & 31;
    const int gid = lane >> 2, tig = lane & 3;
    const int bh  = blockIdx.y;
    const size_t gOff = (size_t)bh * (8192*64);
    const int rowBase = blockIdx.x * 256;

    __half* sKV = smh + H_KV;

    // ldmatrix lane geometry
    const int ar  = (((lane>>3)&1) << 3) + (lane & 7);
    const int ac  = (lane >> 4) << 3;
    const int ar2 = ((lane >> 4) << 3) + (lane & 7);
    const int ac2 = ((lane >> 3) & 1) << 3;
    const uint32_t bKV = s2u(&sKV[ar*SH + ac]);

    // ---- shared prologue: past_kv -> fp16, norm, zero sNrm ----
#pragma unroll
    for (int i = 0; i < 3; i++){
        int f = tid + i * 384;
        if (f < 1024){
            int n = f >> 4, c4 = (f & 15) << 2;
            float4 v = *(const float4*)&pkv[(size_t)bh*4096 + (n << 6) + c4];
            uint2 u;
            u.x = h2u(__floats2half2_rn(v.x, v.y));
            u.y = h2u(__floats2half2_rn(v.z, v.w));
            *(uint2*)&sKV[n*SH + c4] = u;
        }
    }
    if (tid < 64){ sN[tid] = pnorm[bh*64 + tid]; sNrm[tid] = 0.f; }

    const float et  = __expf(-gates[bh & 15]);
    const float gte = 1.f/(1.f+et), omg = et/(1.f+et);

    if (tid < 256){
        // ========== UPDATE GROUP (8 warps): k,v -> new_kv,new_norm ==========
        const int tg2 = tid;
        const int w   = tid >> 5;
        const int m0  = (w & 3) << 4;
        const int coh = (w >> 2) << 5;
        __half* sK = smh + H_K;
        __half* sV = smh + H_V;
        float* stgK = (float*)(smraw + STGK_B);
        float* stgV = (float*)(smraw + STGV_B);
        float* sI  = smf + 64;
        const uint32_t aK  = s2u(&sK[(m0 + ar)*SH + ac]);
        const uint32_t aK2 = s2u(&sK[ar2*SH + m0 + ac2]);
        const uint32_t bV  = s2u(&sV[ar*SH + coh + ac]);
        const uint32_t bKVu = s2u(&sKV[ar*SH + coh + ac]);

        cp_fill256(keys   + gOff + (size_t)rowBase*64, stgK, tg2);
        cp_fill256(values + gOff + (size_t)rowBase*64, stgV, tg2);
        __syncthreads();
        const int c4t = (tg2 & 15) << 2;
        const float n0f = sN[c4t], n1f = sN[c4t+1], n2f = sN[c4t+2], n3f = sN[c4t+3];

        float acc[4][4];
#pragma unroll
        for (int a = 0; a < 4; a++){ acc[a][0]=0.f; acc[a][1]=0.f; acc[a][2]=0.f; acc[a][3]=0.f; }
        float nrm[4] = {0.f, 0.f, 0.f, 0.f};

        for (int ch = 0; ch < 4; ++ch){
            const int row0 = rowBase + (ch << 6);

            // A: k(ch) ready; cvt+denom; prefetch k(ch+1); drain v(ch); barrier
            CP_WAIT(1);
            cvt_denom256(stgK, sK, tg2, lane, n0f, n1f, n2f, n3f, sI, nrm);
            if (ch < 3){
                cp_fill256(keys + gOff + (size_t)(row0+64)*64, stgK, tg2);
                CP_WAIT(1);
            } else {
                CP_WAIT(0);
            }
            bar256();

            // B: GEMM1 quadrant (16 rows x 32 cols) + fused v-update
            {
                const float i1 = sI[m0+gid], i2 = sI[m0+gid+8];
                float c[4][4];
#pragma unroll
                for (int nt = 0; nt < 4; nt++){ c[nt][0]=0.f; c[nt][1]=0.f; c[nt][2]=0.f; c[nt][3]=0.f; }
#pragma unroll
                for (int ks = 0; ks < 4; ks++){
                    const int k0 = ks << 4;
                    uint32_t a0,a1,a2,a3;
                    ldsm4(a0,a1,a2,a3, aK + (k0 << 1));
#pragma unroll
                    for (int ntp = 0; ntp < 2; ntp++){
                        uint32_t b0,b1,b2,b3;
                        ldsm4t(b0,b1,b2,b3, bKVu + ((k0*SH + (ntp<<4)) << 1));
                        mma16(c[2*ntp][0],c[2*ntp][1],c[2*ntp][2],c[2*ntp][3],
                              a0,a1,a2,a3, b0,b1);
                        mma16(c[2*ntp+1][0],c[2*ntp+1][1],c[2*ntp+1][2],c[2*ntp+1][3],
                              a0,a1,a2,a3, b2,b3);
                    }
                }
#pragma unroll
                for (int nt = 0; nt < 4; nt++){
                    const int cc = coh + (nt<<3) + (tig<<1);
                    const float2 v1 = *(const float2*)&stgV[(m0+gid)*SF + cc];
                    const float2 v2 = *(const float2*)&stgV[(m0+gid+8)*SF + cc];
                    __half2 h1 = __floats2half2_rn(v1.x - c[nt][0]*i1,
                                                   v1.y - c[nt][1]*i1);
                    __half2 h2 = __floats2half2_rn(v2.x - c[nt][2]*i2,
                                                   v2.y - c[nt][3]*i2);
                    *(uint32_t*)&sV[(m0+gid)*SH + cc]   = h2u(h1);
                    *(uint32_t*)&sV[(m0+gid+8)*SH + cc] = h2u(h2);
                }
            }
            bar256();
            if (ch < 3)
                cp_fill256(values + gOff + (size_t)(row0+64)*64, stgV, tg2);

            // C: GEMM2 quadrant acc += k^T v (16 d x 32 e)
#pragma unroll
            for (int ks = 0; ks < 4; ks++){
                const int k0 = ks << 4;
                uint32_t a0,a1,a2,a3;
                ldsm4t(a0,a1,a2,a3, aK2 + ((k0*SH) << 1));
#pragma unroll
                for (int ntp = 0; ntp < 2; ntp++){
                    uint32_t b0,b1,b2,b3;
                    ldsm4t(b0,b1,b2,b3, bV + ((k0*SH + (ntp<<4)) << 1));
                    mma16(acc[2*ntp][0],acc[2*ntp][1],acc[2*ntp][2],acc[2*ntp][3],
                          a0,a1,a2,a3, b0,b1);
                    mma16(acc[2*ntp+1][0],acc[2*ntp+1][1],acc[2*ntp+1][2],acc[2*ntp+1][3],
                          a0,a1,a2,a3, b2,b3);
                }
            }
            bar256();
        }

        // ---- flush new_kv / new_norm ----
#pragma unroll
        for (int j = 0; j < 4; j++) atomicAdd(&sNrm[c4t + j], nrm[j]);
        float* kvout = dout + KV_OFF + bh * 4096;
#pragma unroll
        for (int j = 0; j < 4; j++){
            const int cc = coh + (j<<3) + (tig<<1);
            float* r1 = &kvout[(m0+gid)*64 + cc];
            float* r2 = &kvout[(m0+gid+8)*64 + cc];
            atomicAdd(r1,   acc[j][0]); atomicAdd(r1+1, acc[j][1]);
            atomicAdd(r2,   acc[j][2]); atomicAdd(r2+1, acc[j][3]);
        }
        bar256();
        if (tg2 < 64) atomicAdd(&dout[NORM_OFF + bh*64 + tg2], sNrm[tg2]);
    } else {
        // ========== RETRIEVE GROUP (4 warps): q -> gated out ==========
        const int tg = tid & 127;
        const int n0 = ((tid >> 5) - 8) << 4;
        __half* sQ = smh + H_Q;
        float* stgQ = (float*)(smraw + STGQ_B);
        float* stgO = (float*)(smraw + STGO_B);
        float* sI  = smf + 128;
        const uint32_t aQ = s2u(&sQ[(n0 + ar)*SH + ac]);

        cp_fill128(queries + gOff + (size_t)rowBase*64, stgQ, tg);
        cp_fill128(outin   + gOff + (size_t)rowBase*64, stgO, tg);
        __syncthreads();
        const int c4t = (tg & 15) << 2;
        const float n0f = sN[c4t], n1f = sN[c4t+1], n2f = sN[c4t+2], n3f = sN[c4t+3];

        for (int ch = 0; ch < 4; ++ch){
            const int row0 = rowBase + (ch << 6);

            // A: q(ch) ready; cvt+denom; prefetch q(ch+1); drain o(ch); barrier
            CP_WAIT(1);
            cvt_denom128(stgQ, sQ, tg, lane, n0f, n1f, n2f, n3f, sI);
            if (ch < 3){
                cp_fill128(queries + gOff + (size_t)(row0+64)*64, stgQ, tg);
                CP_WAIT(1);
            } else {
                CP_WAIT(0);
            }
            bar128();

            // B: GEMM3 (two 32-col passes) + gated epilogue from staged out
            const float s1 = sI[n0+gid]*omg, s2 = sI[n0+gid+8]*omg;
            const size_t r1 = gOff + (size_t)(row0+n0+gid)*64;
            const size_t r2 = r1 + 512;
#pragma unroll
            for (int pass = 0; pass < 2; pass++){
                float c[4][4];
#pragma unroll
                for (int nt = 0; nt < 4; nt++){ c[nt][0]=0.f; c[nt][1]=0.f; c[nt][2]=0.f; c[nt][3]=0.f; }
#pragma unroll
                for (int ks = 0; ks < 4; ks++){
                    const int k0 = ks << 4;
                    uint32_t a0,a1,a2,a3;
                    ldsm4(a0,a1,a2,a3, aQ + (k0 << 1));
#pragma unroll
                    for (int ntp = 0; ntp < 2; ntp++){
                        uint32_t b0,b1,b2,b3;
                        ldsm4t(b0,b1,b2,b3, bKV + ((k0*SH + (pass<<5) + (ntp<<4)) << 1));
                        mma16(c[2*ntp][0],c[2*ntp][1],c[2*ntp][2],c[2*ntp][3],
                              a0,a1,a2,a3, b0,b1);
                        mma16(c[2*ntp+1][0],c[2*ntp+1][1],c[2*ntp+1][2],c[2*ntp+1][3],
                              a0,a1,a2,a3, b2,b3);
                    }
                }
#pragma unroll
                for (int nt = 0; nt < 4; nt++){
                    const int cc = (pass<<5) + (nt<<3) + (tig<<1);
                    float2 o1 = *(const float2*)&stgO[(n0+gid)*SF + cc];
                    float2 o2 = *(const float2*)&stgO[(n0+gid+8)*SF + cc];
                    o1.x = o1.x*gte + c[nt][0]*s1; o1.y = o1.y*gte + c[nt][1]*s1;
                    o2.x = o2.x*gte + c[nt][2]*s2; o2.y = o2.y*gte + c[nt][3]*s2;
                    *(float2*)&dout[r1 + cc] = o1;
                    *(float2*)&dout[r2 + cc] = o2;
                }
            }
            bar128();
            if (ch < 3)
                cp_fill128(outin + gOff + (size_t)(row0+64)*64, stgO, tg);
        }
    }
}

extern "C" void kernel_launch(void* const* d_in, const int* in_sizes, int n_in,
                              void* d_out, int out_size)
{
    const float* keys    = (const float*)d_in[0];
    const float* values  = (const float*)d_in[1];
    const float* queries = (const float*)d_in[2];
    const float* outin   = (const float*)d_in[3];
    const float* pkv     = (const float*)d_in[4];
    const float* pnorm   = (const float*)d_in[5];
    const float* gates   = (const float*)d_in[6];
    float* dout = (float*)d_out;

    cudaFuncSetAttribute(fw_kernel, cudaFuncAttributeMaxDynamicSharedMemorySize, SMEM_BYTES);

    init_tail<<<1024, 256>>>(pkv, pnorm, dout);
    fw_kernel<<<dim3(32, 64), 384, SMEM_BYTES>>>(keys, values, queries, outin,
                                                 pkv, pnorm, gates, dout);
}